// round 15
// baseline (speedup 1.0000x reference)
#include <cuda_runtime.h>
#include <cuda_bf16.h>

// Problem constants
#define NSPL 191               // 3*64 - 1 spline dims
#define KB   64                // bins
#define ROWF 192               // smem floats per row: 16 chunks of 8 at stride 12

__device__ __forceinline__ float softplus_f(float x) {
    return fmaxf(x, 0.0f) + __logf(1.0f + __expf(-fabsf(x)));
}

// 8-way register select by uniform index k (0..7)
__device__ __forceinline__ float sel8(const float a[8], int k) {
    float x01 = (k & 1) ? a[1] : a[0];
    float x23 = (k & 1) ? a[3] : a[2];
    float x45 = (k & 1) ? a[5] : a[4];
    float x67 = (k & 1) ? a[7] : a[6];
    float y0  = (k & 2) ? x23 : x01;
    float y1  = (k & 2) ? x67 : x45;
    return (k & 4) ? y1 : y0;
}

// 4 cuts per warp. Stage: warp-wide contiguous LDG of each cut's fused
// (ds+sw) w/h cols into warp-private chunk-swizzled smem. Compute: blocked
// bin ownership (lane s owns bins 8s..8s+7) -> LDS.128 + cheap local cumsum.
__global__ __launch_bounds__(256)
void rqs_logdet4b_kernel(const float* __restrict__ value,
                         const float* __restrict__ delta_spline,
                         const int*   __restrict__ genes_oi,
                         const int*   __restrict__ local_gene_ix,
                         const float* __restrict__ spline_weight,
                         float*       __restrict__ out,
                         int n)
{
    const unsigned FULL = 0xffffffffu;
    const float WINDOW_A      = -10000.0f;
    const float INV_AB        = 1.0f / 20000.0f;
    const float MBW           = 0.001f;
    const float MBH           = 0.001f;
    const float MDER          = 0.001f;
    const float DEFAULT_INIT  = 0.53974366f;                 // log(exp(0.999)-1)
    const float OUT_CONST     = -0.69314718f - 9.90348755f;  // LOG_HALF - LOG_AB
    const float cH            = 1.0f - MBH * KB;             // 0.936
    const float cW            = 1.0f - MBW * KB;

    __shared__ __align__(16) float smem[8 * 4 * ROWF];   // 24.6 KB

    const int lane = threadIdx.x & 31;
    int warp = (int)((blockIdx.x * (unsigned)blockDim.x + threadIdx.x) >> 5);
    long long cb = (long long)warp * 4;
    if (cb >= n) return;                         // warp-uniform exit
    float* su = smem + (threadIdx.x >> 5) * (4 * ROWF);

    // ---- prologue: lanes 0..3 fetch per-cut gene + value, broadcast ----
    int   gene_l = 0;
    float val_l  = 0.0f;
    {
        long long ccl = cb + lane;
        int cc = (ccl < n) ? (int)ccl : (n - 1);
        if (lane < 4) {
            gene_l = genes_oi[local_gene_ix[cc]];
            val_l  = value[cc];
        }
    }

    // ---- stage: 4 rows x 128 cols, contiguous LDG, swizzled STS ----
    const int lane_sw = 12 * (lane >> 3) + (lane & 7);   // swizzle of lane part
    #pragma unroll
    for (int r = 0; r < 4; ++r) {
        long long ccl = cb + r;
        int cc = (ccl < n) ? (int)ccl : (n - 1);
        const float* ds = delta_spline + (long long)cc * NSPL;
        const float* sw = spline_weight
                        + (long long)__shfl_sync(FULL, gene_l, r) * NSPL;
        #pragma unroll
        for (int j = 0; j < 4; ++j) {
            int col = 32 * j + lane;
            su[r * ROWF + 48 * j + lane_sw] = ds[col] + sw[col];
        }
    }
    __syncwarp();

    // ---- compute: group g = lanes 8g..8g+7 handles cut cb+g ----
    const int g = lane >> 3;
    const int s = lane & 7;
    long long cutl = cb + g;
    bool active = (cutl < n);
    int cut = active ? (int)cutl : (n - 1);
    const float* rw = su + g * ROWF;

    // widths: chunk s (bins 8s..8s+7), two aligned float4 reads
    float4 wa = *reinterpret_cast<const float4*>(rw + s * 12);
    float4 wb = *reinterpret_cast<const float4*>(rw + s * 12 + 4);
    float Swl = __expf(wa.x) + __expf(wa.y) + __expf(wa.z) + __expf(wa.w)
              + __expf(wb.x) + __expf(wb.y) + __expf(wb.z) + __expf(wb.w);
    #pragma unroll
    for (int o = 4; o; o >>= 1) Swl += __shfl_xor_sync(FULL, Swl, o, 8);

    // heights: chunk 8+s, local running cumsum then width-8 scan of totals
    float4 ha = *reinterpret_cast<const float4*>(rw + 96 + s * 12);
    float4 hb = *reinterpret_cast<const float4*>(rw + 96 + s * 12 + 4);
    float hv[8] = {ha.x, ha.y, ha.z, ha.w, hb.x, hb.y, hb.z, hb.w};
    float cum[8];
    float run = 0.0f;
    #pragma unroll
    for (int k = 0; k < 8; ++k) {
        run += __expf(hv[k]);
        cum[k] = run;
    }
    float incl = run;
    #pragma unroll
    for (int o = 1; o < 8; o <<= 1) {
        float u = __shfl_up_sync(FULL, incl, o, 8);
        if (s >= o) incl += u;
    }
    float excl = incl - run;
    float Sh = __shfl_sync(FULL, incl, 7, 8);
    #pragma unroll
    for (int k = 0; k < 8; ++k) cum[k] += excl;

    // ---- x (broadcast from prologue) ----
    float v  = __shfl_sync(FULL, val_l, g);
    float x  = ((v - WINDOW_A) * INV_AB - 0.5f) * 2.0f;
    bool inside = (x >= -1.0f) && (x <= 1.0f);
    float xc = fminf(fmaxf(x, -1.0f), 1.0f);

    // ---- bin search: bins j=8s+k consecutive ----
    float invSh = __fdividef(1.0f, Sh);
    float ShocH = Sh * (1.0f / cH);
    float stepl = MBH * ShocH;
    float R = (fmaf(xc, 0.5f, 0.5f) - (float)(8 * s + 1) * MBH) * ShocH;
    int cnt = 0;
    #pragma unroll
    for (int k = 0; k < 8; ++k) {
        cnt += (cum[k] <= R);
        R -= stepl;
    }
    #pragma unroll
    for (int o = 4; o; o >>= 1) cnt += __shfl_xor_sync(FULL, cnt, o, 8);
    int idx = min(cnt, 63);                        // group-uniform

    // ---- gathers: bin j owned by lane j>>3, slot j&7 ----
    float cumIdx = __shfl_sync(FULL, sel8(cum, idx & 7), idx >> 3, 8);
    int p = idx - 1;
    float c0 = __shfl_sync(FULL, sel8(cum, p & 7), (p >= 0) ? (p >> 3) : 0, 8);
    if (idx == 0) c0 = 0.0f;
    float eh_g = cumIdx - c0;                      // exp(uh[idx])
    // uw[idx]: group-uniform smem broadcast read (chunk-swizzled address)
    float ew_g = __expf(rw[(idx >> 3) * 12 + (idx & 7)]);

    // ---- derivatives: only 2 scattered loads (ud region never streamed) ----
    const float* ds = delta_spline + (long long)cut * NSPL;
    const float* sw = spline_weight
                    + (long long)__shfl_sync(FULL, gene_l, g) * NSPL;
    int i0 = max(idx - 1, 0);
    int i1 = min(idx, 62);
    float u0 = ds[2 * KB + i0] + sw[2 * KB + i0];
    float u1 = ds[2 * KB + i1] + sw[2 * KB + i1];
    if (idx == 0)  u0 = DEFAULT_INIT;
    if (idx == 63) u1 = DEFAULT_INIT;
    float d0 = MDER + softplus_f(u0);
    float d1 = MDER + softplus_f(u1);

    // ---- spline quantities at idx ----
    float h_sm = fmaf(cH * invSh, eh_g, MBH);
    float w_sm = fmaf(cW, __fdividef(ew_g, Swl), MBW);
    float in_h = 2.0f * h_sm;
    float dlt  = __fdividef(h_sm, w_sm);
    float in_ch = fmaf(2.0f, fmaf(cH * invSh, c0, (float)idx * MBH), -1.0f);

    // ---- rational-quadratic inverse, logabsdet only ----
    float dy = xc - in_ch;
    float sc = d0 + d1 - 2.0f * dlt;
    float a  = dy * sc + in_h * (dlt - d0);
    float b  = in_h * d0 - dy * sc;
    float c  = -dlt * dy;
    float disc = b * b - 4.0f * a * c;
    float root = __fdividef(2.0f * c, -b - sqrtf(fmaxf(disc, 0.0f)));
    float tom  = root * (1.0f - root);
    float denom = dlt + sc * tom;
    float omr  = 1.0f - root;
    float deriv_num = dlt * dlt * (d1 * root * root + 2.0f * dlt * tom + d0 * omr * omr);
    float logabsdet = -(__logf(deriv_num) - 2.0f * __logf(denom));

    float res = OUT_CONST + (inside ? logabsdet : 0.0f);
    if (s == 0 && active) out[cut] = res;          // 4 consecutive floats / warp
}

extern "C" void kernel_launch(void* const* d_in, const int* in_sizes, int n_in,
                              void* d_out, int out_size) {
    const float* value         = (const float*)d_in[0];
    const float* delta_spline  = (const float*)d_in[1];
    const int*   genes_oi      = (const int*)d_in[2];
    const int*   local_gene_ix = (const int*)d_in[3];
    const float* spline_weight = (const float*)d_in[4];
    float* out = (float*)d_out;
    int n = in_sizes[0];                      // N_CUTS
    int blocks = (n + 31) / 32;               // 32 cuts per 256-thread block
    rqs_logdet4b_kernel<<<blocks, 256>>>(value, delta_spline, genes_oi,
                                         local_gene_ix, spline_weight, out, n);
}